// round 1
// baseline (speedup 1.0000x reference)
#include <cuda_runtime.h>

// Problem constants
#define NN 32
#define HH 56
#define WW 56
#define CC 256
#define PP (NN * HH * WW)   // 100352 pixels

// ---------------------------------------------------------------------------
// Scratch: depthwise output [P][C] fp32 (~102.8 MB). Static __device__ array
// (cudaMalloc is forbidden by the harness).
// ---------------------------------------------------------------------------
__device__ float g_dw[(size_t)PP * CC];

// ---------------------------------------------------------------------------
// Packed f32x2 helpers (Blackwell FFMA2 pipe: 2x fp32 MAC per issue)
// ---------------------------------------------------------------------------
__device__ __forceinline__ unsigned long long pack2(float v) {
    unsigned long long r;
    asm("mov.b64 %0, {%1, %1};" : "=l"(r) : "f"(v));
    return r;
}
__device__ __forceinline__ void fma2(unsigned long long& d,
                                     unsigned long long a,
                                     unsigned long long b) {
    asm("fma.rn.f32x2 %0, %1, %2, %0;" : "+l"(d) : "l"(a), "l"(b));
}
__device__ __forceinline__ void unpack2(unsigned long long v, float& lo, float& hi) {
    asm("mov.b64 {%0, %1}, %2;" : "=f"(lo), "=f"(hi) : "l"(v));
}

// ---------------------------------------------------------------------------
// Kernel 1: ReLU + dilated 3x3 depthwise (rate 2, SAME) + dw_bias -> g_dw
// Block: 256 threads, 64 pixels x 256 channels. Each thread owns 4 channels
// (float4) fixed across the block, iterates 16 pixels. Taps preloaded to regs.
// No smem -> full 228KB L1 captures the 9-tap spatial reuse.
// ---------------------------------------------------------------------------
__global__ void __launch_bounds__(256) dw_relu_kernel(
    const float* __restrict__ x,
    const float* __restrict__ dwk,
    const float* __restrict__ dwb)
{
    const int t = threadIdx.x;
    const int c = (t & 63) * 4;     // channel group (float4), fixed per thread
    const int mrow = t >> 6;        // 0..3
    const int pbase = blockIdx.x * 64;

    float4 k[9];
#pragma unroll
    for (int tap = 0; tap < 9; tap++)
        k[tap] = *(const float4*)(dwk + tap * CC + c);
    const float4 bias = *(const float4*)(dwb + c);

#pragma unroll 4
    for (int i = 0; i < 16; i++) {
        const int p  = pbase + mrow + i * 4;
        const int n  = p / (HH * WW);
        const int hw = p % (HH * WW);
        const int h  = hw / WW;
        const int w  = hw % WW;

        float4 acc = bias;
#pragma unroll
        for (int kh = 0; kh < 3; kh++) {
            const int hh = h + 2 * kh - 2;
            if ((unsigned)hh >= (unsigned)HH) continue;
#pragma unroll
            for (int kw = 0; kw < 3; kw++) {
                const int ww = w + 2 * kw - 2;
                if ((unsigned)ww >= (unsigned)WW) continue;
                const float4 v = *(const float4*)(x + ((size_t)((n * HH + hh) * WW + ww)) * CC + c);
                const float4 kk = k[kh * 3 + kw];
                acc.x = fmaf(fmaxf(v.x, 0.0f), kk.x, acc.x);
                acc.y = fmaf(fmaxf(v.y, 0.0f), kk.y, acc.y);
                acc.z = fmaf(fmaxf(v.z, 0.0f), kk.z, acc.z);
                acc.w = fmaf(fmaxf(v.w, 0.0f), kk.w, acc.w);
            }
        }
        *(float4*)(g_dw + (size_t)p * CC + c) = acc;
    }
}

// ---------------------------------------------------------------------------
// Kernel 2: GEMM [P,256] x [256,256] + pw_bias + BN epilogue.
// BM=128, BN=128, BK=16, 256 threads, 8x8 frags as 8x4 packed f32x2 (FFMA2).
// Register-prefetched global tiles overlap compute; single smem buffer.
// ---------------------------------------------------------------------------
#define BM 128
#define BN 128
#define BK 16
#define ASLD 132   // padded stride for sA[k][m] (132*4B, 16B aligned)

__global__ void __launch_bounds__(256) gemm_bn_kernel(
    const float* __restrict__ Bw,     // pw_kernel [256][256], k-major
    const float* __restrict__ pwb,
    const float* __restrict__ gma,
    const float* __restrict__ bta,
    const float* __restrict__ mmean,
    const float* __restrict__ mvar,
    float* __restrict__ out)
{
    __shared__ float sA[BK * ASLD];
    __shared__ float sB[BK * BN];

    const int t  = threadIdx.x;
    const int tx = t & 15;
    const int ty = t >> 4;
    const int bm = blockIdx.x * BM;
    const int bn = blockIdx.y * BN;

    unsigned long long acc[8][4];
#pragma unroll
    for (int i = 0; i < 8; i++)
#pragma unroll
        for (int j = 0; j < 4; j++) acc[i][j] = 0ULL;

    // cooperative-load addressing (2 float4 per thread for each of A, B)
    int arow[2], acol[2], brow[2], bcol[2];
#pragma unroll
    for (int j = 0; j < 2; j++) {
        const int q = t + 256 * j;
        arow[j] = q >> 2;           // 0..127
        acol[j] = (q & 3) * 4;      // 0,4,8,12
        brow[j] = q >> 5;           // 0..15
        bcol[j] = (q & 31) * 4;     // 0..124
    }

    float4 pa[2], pb[2];
    // prologue: load tile 0
#pragma unroll
    for (int j = 0; j < 2; j++) {
        pa[j] = *(const float4*)(g_dw + (size_t)(bm + arow[j]) * CC + acol[j]);
        pb[j] = *(const float4*)(Bw + (size_t)brow[j] * CC + bn + bcol[j]);
    }
#pragma unroll
    for (int j = 0; j < 2; j++) {
        sA[(acol[j] + 0) * ASLD + arow[j]] = pa[j].x;
        sA[(acol[j] + 1) * ASLD + arow[j]] = pa[j].y;
        sA[(acol[j] + 2) * ASLD + arow[j]] = pa[j].z;
        sA[(acol[j] + 3) * ASLD + arow[j]] = pa[j].w;
        *(float4*)(sB + brow[j] * BN + bcol[j]) = pb[j];
    }
    __syncthreads();

    const int NT = CC / BK;  // 16 tiles
    for (int kt = 0; kt < NT; kt++) {
        // prefetch next tile into registers (overlaps with compute below)
        if (kt < NT - 1) {
            const int k0n = (kt + 1) * BK;
#pragma unroll
            for (int j = 0; j < 2; j++) {
                pa[j] = *(const float4*)(g_dw + (size_t)(bm + arow[j]) * CC + k0n + acol[j]);
                pb[j] = *(const float4*)(Bw + (size_t)(k0n + brow[j]) * CC + bn + bcol[j]);
            }
        }

#pragma unroll
        for (int kk = 0; kk < BK; kk++) {
            const float4 a0 = *(const float4*)(sA + kk * ASLD + tx * 4);
            const float4 a1 = *(const float4*)(sA + kk * ASLD + 64 + tx * 4);
            const ulonglong2 b0 = *(const ulonglong2*)(sB + kk * BN + ty * 4);
            const ulonglong2 b1 = *(const ulonglong2*)(sB + kk * BN + 64 + ty * 4);

            unsigned long long pav[8];
            pav[0] = pack2(a0.x); pav[1] = pack2(a0.y);
            pav[2] = pack2(a0.z); pav[3] = pack2(a0.w);
            pav[4] = pack2(a1.x); pav[5] = pack2(a1.y);
            pav[6] = pack2(a1.z); pav[7] = pack2(a1.w);
            const unsigned long long bv[4] = {b0.x, b0.y, b1.x, b1.y};

#pragma unroll
            for (int mi = 0; mi < 8; mi++)
#pragma unroll
                for (int nj = 0; nj < 4; nj++)
                    fma2(acc[mi][nj], pav[mi], bv[nj]);
        }
        __syncthreads();

        if (kt < NT - 1) {
#pragma unroll
            for (int j = 0; j < 2; j++) {
                sA[(acol[j] + 0) * ASLD + arow[j]] = pa[j].x;
                sA[(acol[j] + 1) * ASLD + arow[j]] = pa[j].y;
                sA[(acol[j] + 2) * ASLD + arow[j]] = pa[j].z;
                sA[(acol[j] + 3) * ASLD + arow[j]] = pa[j].w;
                *(float4*)(sB + brow[j] * BN + bcol[j]) = pb[j];
            }
            __syncthreads();
        }
    }

    // Epilogue: out = acc*inv + (pwb*inv + beta - mean*inv), inv = gamma*rsqrt(var+eps)
    float inv[8], b2[8];
#pragma unroll
    for (int nj = 0; nj < 8; nj++) {
        const int nl = (nj < 4) ? (ty * 4 + nj) : (64 + ty * 4 + (nj - 4));
        const int n  = bn + nl;
        const float iv = gma[n] * rsqrtf(mvar[n] + 1e-3f);
        inv[nj] = iv;
        b2[nj]  = fmaf(pwb[n], iv, bta[n] - mmean[n] * iv);
    }

#pragma unroll
    for (int mi = 0; mi < 8; mi++) {
        const int ml = (mi < 4) ? (tx * 4 + mi) : (64 + tx * 4 + (mi - 4));
        const int m  = bm + ml;
        float v[8];
        unpack2(acc[mi][0], v[0], v[1]);
        unpack2(acc[mi][1], v[2], v[3]);
        unpack2(acc[mi][2], v[4], v[5]);
        unpack2(acc[mi][3], v[6], v[7]);

        float4 o0, o1;
        o0.x = fmaf(v[0], inv[0], b2[0]);
        o0.y = fmaf(v[1], inv[1], b2[1]);
        o0.z = fmaf(v[2], inv[2], b2[2]);
        o0.w = fmaf(v[3], inv[3], b2[3]);
        o1.x = fmaf(v[4], inv[4], b2[4]);
        o1.y = fmaf(v[5], inv[5], b2[5]);
        o1.z = fmaf(v[6], inv[6], b2[6]);
        o1.w = fmaf(v[7], inv[7], b2[7]);

        *(float4*)(out + (size_t)m * CC + bn + ty * 4)      = o0;
        *(float4*)(out + (size_t)m * CC + bn + 64 + ty * 4) = o1;
    }
}

// ---------------------------------------------------------------------------
// Launch
// ---------------------------------------------------------------------------
extern "C" void kernel_launch(void* const* d_in, const int* in_sizes, int n_in,
                              void* d_out, int out_size)
{
    const float* x     = (const float*)d_in[0];
    const float* dwk   = (const float*)d_in[1];
    const float* dwb   = (const float*)d_in[2];
    const float* pwk   = (const float*)d_in[3];
    const float* pwb   = (const float*)d_in[4];
    const float* gma   = (const float*)d_in[5];
    const float* bta   = (const float*)d_in[6];
    const float* mmean = (const float*)d_in[7];
    const float* mvar  = (const float*)d_in[8];
    float* out = (float*)d_out;

    dw_relu_kernel<<<PP / 64, 256>>>(x, dwk, dwb);
    gemm_bn_kernel<<<dim3(PP / BM, CC / BN), 256>>>(pwk, pwb, gma, bta, mmean, mvar, out);
}

// round 3
// speedup vs baseline: 1.7376x; 1.7376x over previous
#include <cuda_runtime.h>
#include <cuda_bf16.h>
#include <cstdint>

// Problem constants
#define NN 32
#define HH 56
#define WW 56
#define CC 256
#define PP (NN * HH * WW)   // 100352 pixels

// ---------------------------------------------------------------------------
// Scratch: depthwise output split into bf16 hi/lo (a = hi + lo), and
// transposed+split pointwise weights B[n][k].
// ---------------------------------------------------------------------------
__device__ __align__(256) __nv_bfloat16 g_ahi[(size_t)PP * CC];
__device__ __align__(256) __nv_bfloat16 g_alo[(size_t)PP * CC];
__device__ __align__(256) __nv_bfloat16 g_bh[CC * CC];
__device__ __align__(256) __nv_bfloat16 g_bl[CC * CC];

// ---------------------------------------------------------------------------
// PTX helpers
// ---------------------------------------------------------------------------
__device__ __forceinline__ uint32_t smem_u32(const void* p) {
    uint32_t a;
    asm("{ .reg .u64 t; cvta.to.shared.u64 t, %1; cvt.u32.u64 %0, t; }"
        : "=r"(a) : "l"(p));
    return a;
}
#define CP16(sa, gp) \
    asm volatile("cp.async.cg.shared.global [%0], [%1], 16;" \
                 :: "r"((uint32_t)(sa)), "l"(gp) : "memory")
#define CP_COMMIT() asm volatile("cp.async.commit_group;" ::: "memory")
#define CP_WAIT1()  asm volatile("cp.async.wait_group 1;" ::: "memory")
#define CP_WAIT0()  asm volatile("cp.async.wait_group 0;" ::: "memory")

__device__ __forceinline__ uint32_t lds32(uint32_t a) {
    uint32_t v;
    asm volatile("ld.shared.b32 %0, [%1];" : "=r"(v) : "r"(a));
    return v;
}
__device__ __forceinline__ void mma16816(float c[4],
                                         uint32_t a0, uint32_t a1, uint32_t a2, uint32_t a3,
                                         uint32_t b0, uint32_t b1) {
    asm volatile(
        "mma.sync.aligned.m16n8k16.row.col.f32.bf16.bf16.f32 "
        "{%0,%1,%2,%3}, {%4,%5,%6,%7}, {%8,%9}, {%0,%1,%2,%3};"
        : "+f"(c[0]), "+f"(c[1]), "+f"(c[2]), "+f"(c[3])
        : "r"(a0), "r"(a1), "r"(a2), "r"(a3), "r"(b0), "r"(b1));
}

// ---------------------------------------------------------------------------
// bf16 hi/lo split store helper
// ---------------------------------------------------------------------------
__device__ __forceinline__ void split_store4(__nv_bfloat16* ph, __nv_bfloat16* pl, float4 v) {
    __nv_bfloat16 h0 = __float2bfloat16_rn(v.x);
    __nv_bfloat16 h1 = __float2bfloat16_rn(v.y);
    __nv_bfloat16 h2 = __float2bfloat16_rn(v.z);
    __nv_bfloat16 h3 = __float2bfloat16_rn(v.w);
    __nv_bfloat16 l0 = __float2bfloat16_rn(v.x - __bfloat162float(h0));
    __nv_bfloat16 l1 = __float2bfloat16_rn(v.y - __bfloat162float(h1));
    __nv_bfloat16 l2 = __float2bfloat16_rn(v.z - __bfloat162float(h2));
    __nv_bfloat16 l3 = __float2bfloat16_rn(v.w - __bfloat162float(h3));
    __nv_bfloat162 hv0 = __nv_bfloat162(h0, h1), hv1 = __nv_bfloat162(h2, h3);
    __nv_bfloat162 lv0 = __nv_bfloat162(l0, l1), lv1 = __nv_bfloat162(l2, l3);
    uint2 hu, lu;
    hu.x = *(uint32_t*)&hv0; hu.y = *(uint32_t*)&hv1;
    lu.x = *(uint32_t*)&lv0; lu.y = *(uint32_t*)&lv1;
    *(uint2*)ph = hu;
    *(uint2*)pl = lu;
}

// ---------------------------------------------------------------------------
// Kernel 0: transpose + bf16-split pw_kernel -> g_bh/g_bl [n][k]
// ---------------------------------------------------------------------------
__global__ void __launch_bounds__(256) bprep_kernel(const float* __restrict__ pwk) {
    const int idx = blockIdx.x * 256 + threadIdx.x;  // 65536 total
    const int k = idx >> 8, n = idx & 255;
    const float v = pwk[(size_t)k * CC + n];
    const __nv_bfloat16 h = __float2bfloat16_rn(v);
    const __nv_bfloat16 l = __float2bfloat16_rn(v - __bfloat162float(h));
    g_bh[(size_t)n * CC + k] = h;
    g_bl[(size_t)n * CC + k] = l;
}

// ---------------------------------------------------------------------------
// Kernel 1: ReLU + dilated 3x3 depthwise (rate 2) + dw_bias -> bf16 hi/lo.
// 8 consecutive w pixels per thread share input columns (12 loads / 24 taps).
// ---------------------------------------------------------------------------
__global__ void __launch_bounds__(256) dw_relu_kernel(
    const float* __restrict__ x,
    const float* __restrict__ dwk,
    const float* __restrict__ dwb)
{
    const int t = threadIdx.x;
    const int c = (t & 63) * 4;                    // channel group
    const int oct = blockIdx.x * 4 + (t >> 6);     // 0..12543
    const int w0 = (oct % 7) * 8;
    const int nh = oct / 7;
    const int h = nh % HH;
    const int n = nh / HH;

    float4 k[9];
#pragma unroll
    for (int tap = 0; tap < 9; tap++)
        k[tap] = *(const float4*)(dwk + tap * CC + c);
    const float4 bias = *(const float4*)(dwb + c);

    float4 acc[8];
#pragma unroll
    for (int px = 0; px < 8; px++) acc[px] = bias;

#pragma unroll
    for (int kh = 0; kh < 3; kh++) {
        const int hh = h + 2 * kh - 2;
        if ((unsigned)hh >= (unsigned)HH) continue;
        const float* xrow = x + ((size_t)(n * HH + hh) * WW) * CC + c;

        float4 col[12];
#pragma unroll
        for (int j = 0; j < 12; j++) {
            const int ww = w0 - 2 + j;
            if ((unsigned)ww < (unsigned)WW) {
                float4 v = *(const float4*)(xrow + (size_t)ww * CC);
                v.x = fmaxf(v.x, 0.0f); v.y = fmaxf(v.y, 0.0f);
                v.z = fmaxf(v.z, 0.0f); v.w = fmaxf(v.w, 0.0f);
                col[j] = v;
            } else {
                col[j] = make_float4(0.f, 0.f, 0.f, 0.f);
            }
        }
        const float4 k0 = k[kh * 3 + 0], k1 = k[kh * 3 + 1], k2 = k[kh * 3 + 2];
#pragma unroll
        for (int px = 0; px < 8; px++) {
            acc[px].x = fmaf(col[px].x, k0.x, fmaf(col[px + 2].x, k1.x, fmaf(col[px + 4].x, k2.x, acc[px].x)));
            acc[px].y = fmaf(col[px].y, k0.y, fmaf(col[px + 2].y, k1.y, fmaf(col[px + 4].y, k2.y, acc[px].y)));
            acc[px].z = fmaf(col[px].z, k0.z, fmaf(col[px + 2].z, k1.z, fmaf(col[px + 4].z, k2.z, acc[px].z)));
            acc[px].w = fmaf(col[px].w, k0.w, fmaf(col[px + 2].w, k1.w, fmaf(col[px + 4].w, k2.w, acc[px].w)));
        }
    }

    const size_t base = ((size_t)(n * HH + h) * WW + w0) * CC + c;
#pragma unroll
    for (int px = 0; px < 8; px++)
        split_store4(g_ahi + base + (size_t)px * CC, g_alo + base + (size_t)px * CC, acc[px]);
}

// ---------------------------------------------------------------------------
// Kernel 2: HMMA (mma.sync bf16) split-GEMM [P,256]x[256,256] + bias + BN.
// CTA 128x128, 8 warps (2m x 4n), warp tile 64x32, K chunks of 32,
// cp.async double buffering. Smem rows padded to 80B (bank-conflict-free).
// ---------------------------------------------------------------------------
#define STRIDE 80
#define TILE_B (128 * STRIDE)          // 10240 bytes per [128][32] bf16 tile
#define STAGE_B (4 * TILE_B)           // Ah, Al, Bh, Bl
#define OFF_AL TILE_B
#define OFF_BH (2 * TILE_B)
#define OFF_BL (3 * TILE_B)
#define OFF_INV (2 * STAGE_B)          // 81920
#define OFF_B2  (OFF_INV + 512)
#define SMEM_BYTES (OFF_B2 + 512)      // 82944

__global__ void __launch_bounds__(256, 2) gemm_mma_kernel(
    const float* __restrict__ pwb,
    const float* __restrict__ gma,
    const float* __restrict__ bta,
    const float* __restrict__ mmean,
    const float* __restrict__ mvar,
    float* __restrict__ out)
{
    extern __shared__ __align__(128) char smem[];
    const uint32_t sb = smem_u32(smem);
    const int t = threadIdx.x;
    const int lane = t & 31, wid = t >> 5;
    const int wm = wid & 1, wn = wid >> 1;
    const int r = lane >> 2, tg = lane & 3;
    const int bm = blockIdx.x * 128;
    const int bn = blockIdx.y * 128;

    // BN constants
    float* sinv = (float*)(smem + OFF_INV);
    float* sbb  = (float*)(smem + OFF_B2);
    if (t < 128) {
        const int nn = bn + t;
        const float iv = gma[nn] * rsqrtf(mvar[nn] + 1e-3f);
        sinv[t] = iv;
        sbb[t]  = fmaf(pwb[nn], iv, bta[nn] - mmean[nn] * iv);
    }

    // loader addressing: thread t -> row t>>1, 32B half (t&1)
    const int lrow = t >> 1, lhalf = t & 1;
    const __nv_bfloat16* gAh = g_ahi + (size_t)(bm + lrow) * CC + lhalf * 16;
    const __nv_bfloat16* gAl = g_alo + (size_t)(bm + lrow) * CC + lhalf * 16;
    const __nv_bfloat16* gBh = g_bh  + (size_t)(bn + lrow) * CC + lhalf * 16;
    const __nv_bfloat16* gBl = g_bl  + (size_t)(bn + lrow) * CC + lhalf * 16;
    const uint32_t sdst = sb + lrow * STRIDE + lhalf * 32;

#define ISSUE(cix) do {                                                     \
    const int _st = ((cix) & 1) * STAGE_B;                                  \
    const int _k0 = (cix) * 32;                                             \
    CP16(sdst + _st + 0,            gAh + _k0);                             \
    CP16(sdst + _st + 16,           gAh + _k0 + 8);                         \
    CP16(sdst + _st + OFF_AL,       gAl + _k0);                             \
    CP16(sdst + _st + OFF_AL + 16,  gAl + _k0 + 8);                         \
    CP16(sdst + _st + OFF_BH,       gBh + _k0);                             \
    CP16(sdst + _st + OFF_BH + 16,  gBh + _k0 + 8);                         \
    CP16(sdst + _st + OFF_BL,       gBl + _k0);                             \
    CP16(sdst + _st + OFF_BL + 16,  gBl + _k0 + 8);                         \
    CP_COMMIT();                                                            \
} while (0)

    ISSUE(0);

    float acc[4][4][4];
#pragma unroll
    for (int mt = 0; mt < 4; mt++)
#pragma unroll
        for (int nt = 0; nt < 4; nt++)
#pragma unroll
            for (int i = 0; i < 4; i++) acc[mt][nt][i] = 0.0f;

    const uint32_t aBase = sb + (wm * 64 + r) * STRIDE + tg * 4;
    const uint32_t bBase = sb + (wn * 32 + r) * STRIDE + tg * 4;

    for (int c = 0; c < 8; c++) {
        if (c < 7) { ISSUE(c + 1); CP_WAIT1(); } else { CP_WAIT0(); }
        __syncthreads();

        const uint32_t st = (uint32_t)((c & 1) * STAGE_B);
#pragma unroll
        for (int k16 = 0; k16 < 2; k16++) {
            const uint32_t kb = k16 * 32;
            uint32_t bh0[4], bh1[4], bl0[4], bl1[4];
#pragma unroll
            for (int nt = 0; nt < 4; nt++) {
                const uint32_t o = bBase + st + OFF_BH + nt * (8 * STRIDE) + kb;
                bh0[nt] = lds32(o);
                bh1[nt] = lds32(o + 16);
                bl0[nt] = lds32(o + TILE_B);
                bl1[nt] = lds32(o + TILE_B + 16);
            }
#pragma unroll
            for (int mt = 0; mt < 4; mt++) {
                const uint32_t o = aBase + st + mt * (16 * STRIDE) + kb;
                const uint32_t ah0 = lds32(o);
                const uint32_t ah1 = lds32(o + 8 * STRIDE);
                const uint32_t ah2 = lds32(o + 16);
                const uint32_t ah3 = lds32(o + 8 * STRIDE + 16);
                const uint32_t al0 = lds32(o + OFF_AL);
                const uint32_t al1 = lds32(o + OFF_AL + 8 * STRIDE);
                const uint32_t al2 = lds32(o + OFF_AL + 16);
                const uint32_t al3 = lds32(o + OFF_AL + 8 * STRIDE + 16);
#pragma unroll
                for (int nt = 0; nt < 4; nt++) {
                    mma16816(acc[mt][nt], ah0, ah1, ah2, ah3, bh0[nt], bh1[nt]);
                    mma16816(acc[mt][nt], ah0, ah1, ah2, ah3, bl0[nt], bl1[nt]);
                    mma16816(acc[mt][nt], al0, al1, al2, al3, bh0[nt], bh1[nt]);
                }
            }
        }
        __syncthreads();
    }

    // Epilogue: BN scale/offset + store
#pragma unroll
    for (int mt = 0; mt < 4; mt++) {
        const int row0 = bm + wm * 64 + mt * 16 + r;
#pragma unroll
        for (int nt = 0; nt < 4; nt++) {
            const int cl = wn * 32 + nt * 8 + tg * 2;   // local col
            const float i0 = sinv[cl], i1 = sinv[cl + 1];
            const float o0 = sbb[cl],  o1 = sbb[cl + 1];
            float2 v0, v1;
            v0.x = fmaf(acc[mt][nt][0], i0, o0);
            v0.y = fmaf(acc[mt][nt][1], i1, o1);
            v1.x = fmaf(acc[mt][nt][2], i0, o0);
            v1.y = fmaf(acc[mt][nt][3], i1, o1);
            *(float2*)(out + (size_t)row0 * CC + bn + cl)       = v0;
            *(float2*)(out + (size_t)(row0 + 8) * CC + bn + cl) = v1;
        }
    }
#undef ISSUE
}

// ---------------------------------------------------------------------------
// Launch
// ---------------------------------------------------------------------------
extern "C" void kernel_launch(void* const* d_in, const int* in_sizes, int n_in,
                              void* d_out, int out_size)
{
    const float* x     = (const float*)d_in[0];
    const float* dwk   = (const float*)d_in[1];
    const float* dwb   = (const float*)d_in[2];
    const float* pwk   = (const float*)d_in[3];
    const float* pwb   = (const float*)d_in[4];
    const float* gma   = (const float*)d_in[5];
    const float* bta   = (const float*)d_in[6];
    const float* mmean = (const float*)d_in[7];
    const float* mvar  = (const float*)d_in[8];
    float* out = (float*)d_out;

    static int smem_set = 0;
    if (!smem_set) {
        cudaFuncSetAttribute(gemm_mma_kernel,
                             cudaFuncAttributeMaxDynamicSharedMemorySize, SMEM_BYTES);
        smem_set = 1;
    }

    bprep_kernel<<<256, 256>>>(pwk);
    dw_relu_kernel<<<3136, 256>>>(x, dwk, dwb);
    gemm_mma_kernel<<<dim3(PP / 128, 2), 256, SMEM_BYTES>>>(
        pwb, gma, bta, mmean, mvar, out);
}

// round 4
// speedup vs baseline: 1.8366x; 1.0570x over previous
#include <cuda_runtime.h>
#include <cuda_bf16.h>
#include <cstdint>

// Problem constants
#define NN 32
#define HH 56
#define WW 56
#define CC 256
#define PP (NN * HH * WW)   // 100352 pixels

// ---------------------------------------------------------------------------
// Scratch: depthwise output split into bf16 hi/lo (a = hi + lo), and
// transposed+split pointwise weights B[n][k].
// ---------------------------------------------------------------------------
__device__ __align__(256) __nv_bfloat16 g_ahi[(size_t)PP * CC];
__device__ __align__(256) __nv_bfloat16 g_alo[(size_t)PP * CC];
__device__ __align__(256) __nv_bfloat16 g_bh[CC * CC];
__device__ __align__(256) __nv_bfloat16 g_bl[CC * CC];

// ---------------------------------------------------------------------------
// PTX helpers
// ---------------------------------------------------------------------------
__device__ __forceinline__ uint32_t smem_u32(const void* p) {
    uint32_t a;
    asm("{ .reg .u64 t; cvta.to.shared.u64 t, %1; cvt.u32.u64 %0, t; }"
        : "=r"(a) : "l"(p));
    return a;
}
#define CP16(sa, gp) \
    asm volatile("cp.async.cg.shared.global [%0], [%1], 16;" \
                 :: "r"((uint32_t)(sa)), "l"(gp) : "memory")
#define CP_COMMIT() asm volatile("cp.async.commit_group;" ::: "memory")
#define CP_WAIT1()  asm volatile("cp.async.wait_group 1;" ::: "memory")
#define CP_WAIT0()  asm volatile("cp.async.wait_group 0;" ::: "memory")

__device__ __forceinline__ void ldsm4(uint32_t r[4], uint32_t a) {
    asm volatile("ldmatrix.sync.aligned.m8n8.x4.shared.b16 {%0,%1,%2,%3}, [%4];"
                 : "=r"(r[0]), "=r"(r[1]), "=r"(r[2]), "=r"(r[3]) : "r"(a));
}
__device__ __forceinline__ void mma16816(float c[4],
                                         uint32_t a0, uint32_t a1, uint32_t a2, uint32_t a3,
                                         uint32_t b0, uint32_t b1) {
    asm volatile(
        "mma.sync.aligned.m16n8k16.row.col.f32.bf16.bf16.f32 "
        "{%0,%1,%2,%3}, {%4,%5,%6,%7}, {%8,%9}, {%0,%1,%2,%3};"
        : "+f"(c[0]), "+f"(c[1]), "+f"(c[2]), "+f"(c[3])
        : "r"(a0), "r"(a1), "r"(a2), "r"(a3), "r"(b0), "r"(b1));
}

// ---------------------------------------------------------------------------
// bf16 hi/lo split store helper
// ---------------------------------------------------------------------------
__device__ __forceinline__ void split_store4(__nv_bfloat16* ph, __nv_bfloat16* pl, float4 v) {
    __nv_bfloat16 h0 = __float2bfloat16_rn(v.x);
    __nv_bfloat16 h1 = __float2bfloat16_rn(v.y);
    __nv_bfloat16 h2 = __float2bfloat16_rn(v.z);
    __nv_bfloat16 h3 = __float2bfloat16_rn(v.w);
    __nv_bfloat16 l0 = __float2bfloat16_rn(v.x - __bfloat162float(h0));
    __nv_bfloat16 l1 = __float2bfloat16_rn(v.y - __bfloat162float(h1));
    __nv_bfloat16 l2 = __float2bfloat16_rn(v.z - __bfloat162float(h2));
    __nv_bfloat16 l3 = __float2bfloat16_rn(v.w - __bfloat162float(h3));
    __nv_bfloat162 hv0 = __nv_bfloat162(h0, h1), hv1 = __nv_bfloat162(h2, h3);
    __nv_bfloat162 lv0 = __nv_bfloat162(l0, l1), lv1 = __nv_bfloat162(l2, l3);
    uint2 hu, lu;
    hu.x = *(uint32_t*)&hv0; hu.y = *(uint32_t*)&hv1;
    lu.x = *(uint32_t*)&lv0; lu.y = *(uint32_t*)&lv1;
    *(uint2*)ph = hu;
    *(uint2*)pl = lu;
}

// ---------------------------------------------------------------------------
// Kernel 0: transpose + bf16-split pw_kernel -> g_bh/g_bl [n][k]
// ---------------------------------------------------------------------------
__global__ void __launch_bounds__(256) bprep_kernel(const float* __restrict__ pwk) {
    const int idx = blockIdx.x * 256 + threadIdx.x;  // 65536 total
    const int k = idx >> 8, n = idx & 255;
    const float v = pwk[(size_t)k * CC + n];
    const __nv_bfloat16 h = __float2bfloat16_rn(v);
    const __nv_bfloat16 l = __float2bfloat16_rn(v - __bfloat162float(h));
    g_bh[(size_t)n * CC + k] = h;
    g_bl[(size_t)n * CC + k] = l;
}

// ---------------------------------------------------------------------------
// Kernel 1: ReLU + dilated 3x3 depthwise (rate 2) + dw_bias -> bf16 hi/lo.
// 8 consecutive w pixels per thread share input columns (12 loads / 24 taps).
// ---------------------------------------------------------------------------
__global__ void __launch_bounds__(256) dw_relu_kernel(
    const float* __restrict__ x,
    const float* __restrict__ dwk,
    const float* __restrict__ dwb)
{
    const int t = threadIdx.x;
    const int c = (t & 63) * 4;                    // channel group
    const int oct = blockIdx.x * 4 + (t >> 6);     // 0..12543
    const int w0 = (oct % 7) * 8;
    const int nh = oct / 7;
    const int h = nh % HH;
    const int n = nh / HH;

    float4 k[9];
#pragma unroll
    for (int tap = 0; tap < 9; tap++)
        k[tap] = *(const float4*)(dwk + tap * CC + c);
    const float4 bias = *(const float4*)(dwb + c);

    float4 acc[8];
#pragma unroll
    for (int px = 0; px < 8; px++) acc[px] = bias;

#pragma unroll
    for (int kh = 0; kh < 3; kh++) {
        const int hh = h + 2 * kh - 2;
        if ((unsigned)hh >= (unsigned)HH) continue;
        const float* xrow = x + ((size_t)(n * HH + hh) * WW) * CC + c;

        float4 col[12];
#pragma unroll
        for (int j = 0; j < 12; j++) {
            const int ww = w0 - 2 + j;
            if ((unsigned)ww < (unsigned)WW) {
                float4 v = *(const float4*)(xrow + (size_t)ww * CC);
                v.x = fmaxf(v.x, 0.0f); v.y = fmaxf(v.y, 0.0f);
                v.z = fmaxf(v.z, 0.0f); v.w = fmaxf(v.w, 0.0f);
                col[j] = v;
            } else {
                col[j] = make_float4(0.f, 0.f, 0.f, 0.f);
            }
        }
        const float4 k0 = k[kh * 3 + 0], k1 = k[kh * 3 + 1], k2 = k[kh * 3 + 2];
#pragma unroll
        for (int px = 0; px < 8; px++) {
            acc[px].x = fmaf(col[px].x, k0.x, fmaf(col[px + 2].x, k1.x, fmaf(col[px + 4].x, k2.x, acc[px].x)));
            acc[px].y = fmaf(col[px].y, k0.y, fmaf(col[px + 2].y, k1.y, fmaf(col[px + 4].y, k2.y, acc[px].y)));
            acc[px].z = fmaf(col[px].z, k0.z, fmaf(col[px + 2].z, k1.z, fmaf(col[px + 4].z, k2.z, acc[px].z)));
            acc[px].w = fmaf(col[px].w, k0.w, fmaf(col[px + 2].w, k1.w, fmaf(col[px + 4].w, k2.w, acc[px].w)));
        }
    }

    const size_t base = ((size_t)(n * HH + h) * WW + w0) * CC + c;
#pragma unroll
    for (int px = 0; px < 8; px++)
        split_store4(g_ahi + base + (size_t)px * CC, g_alo + base + (size_t)px * CC, acc[px]);
}

// ---------------------------------------------------------------------------
// Kernel 2: HMMA split-GEMM [P,256]x[256,256] + bias + BN.
// CTA 128x128, 8 warps (2m x 4n), warp tile 64x32, K chunks of 32,
// cp.async double buffering, ldmatrix.x4 fragment loads.
// Smem rows padded to 80B (conflict-free for ldmatrix 8-row phases).
// Grid is (bn=2, bm=784): the 2 CTAs sharing an A tile run adjacently -> L2 reuse.
// ---------------------------------------------------------------------------
#define STRIDE 80
#define TILE_B (128 * STRIDE)          // 10240 bytes per [128][32] bf16 tile
#define STAGE_B (4 * TILE_B)           // Ah, Al, Bh, Bl
#define OFF_AL TILE_B
#define OFF_BH (2 * TILE_B)
#define OFF_BL (3 * TILE_B)
#define OFF_INV (2 * STAGE_B)          // 81920
#define OFF_B2  (OFF_INV + 512)
#define SMEM_BYTES (OFF_B2 + 512)      // 82944

__global__ void __launch_bounds__(256, 2) gemm_mma_kernel(
    const float* __restrict__ pwb,
    const float* __restrict__ gma,
    const float* __restrict__ bta,
    const float* __restrict__ mmean,
    const float* __restrict__ mvar,
    float* __restrict__ out)
{
    extern __shared__ __align__(128) char smem[];
    const uint32_t sb = smem_u32(smem);
    const int t = threadIdx.x;
    const int lane = t & 31, wid = t >> 5;
    const int wm = wid & 1, wn = wid >> 1;
    const int r = lane >> 2, tg = lane & 3;
    const int bn = blockIdx.x * 128;
    const int bm = blockIdx.y * 128;

    // BN constants
    float* sinv = (float*)(smem + OFF_INV);
    float* sbb  = (float*)(smem + OFF_B2);
    if (t < 128) {
        const int nn = bn + t;
        const float iv = gma[nn] * rsqrtf(mvar[nn] + 1e-3f);
        sinv[t] = iv;
        sbb[t]  = fmaf(pwb[nn], iv, bta[nn] - mmean[nn] * iv);
    }

    // loader addressing: thread t -> row t>>1, 32B half (t&1)
    const int lrow = t >> 1, lhalf = t & 1;
    const __nv_bfloat16* gAh = g_ahi + (size_t)(bm + lrow) * CC + lhalf * 16;
    const __nv_bfloat16* gAl = g_alo + (size_t)(bm + lrow) * CC + lhalf * 16;
    const __nv_bfloat16* gBh = g_bh  + (size_t)(bn + lrow) * CC + lhalf * 16;
    const __nv_bfloat16* gBl = g_bl  + (size_t)(bn + lrow) * CC + lhalf * 16;
    const uint32_t sdst = sb + lrow * STRIDE + lhalf * 32;

#define ISSUE(cix) do {                                                     \
    const int _st = ((cix) & 1) * STAGE_B;                                  \
    const int _k0 = (cix) * 32;                                             \
    CP16(sdst + _st + 0,            gAh + _k0);                             \
    CP16(sdst + _st + 16,           gAh + _k0 + 8);                         \
    CP16(sdst + _st + OFF_AL,       gAl + _k0);                             \
    CP16(sdst + _st + OFF_AL + 16,  gAl + _k0 + 8);                         \
    CP16(sdst + _st + OFF_BH,       gBh + _k0);                             \
    CP16(sdst + _st + OFF_BH + 16,  gBh + _k0 + 8);                         \
    CP16(sdst + _st + OFF_BL,       gBl + _k0);                             \
    CP16(sdst + _st + OFF_BL + 16,  gBl + _k0 + 8);                         \
    CP_COMMIT();                                                            \
} while (0)

    ISSUE(0);

    float acc[4][4][4];
#pragma unroll
    for (int mt = 0; mt < 4; mt++)
#pragma unroll
        for (int nt = 0; nt < 4; nt++)
#pragma unroll
            for (int i = 0; i < 4; i++) acc[mt][nt][i] = 0.0f;

    // ldmatrix lane addresses (offsets within a stage)
    // A: matrices (m0-7,k0-7),(m8-15,k0-7),(m0-7,k8-15),(m8-15,k8-15)
    const uint32_t aAddr = sb + (wm * 64 + (lane & 15)) * STRIDE + (lane >> 4) * 16;
    // B: matrices (n0-7,k0-7),(n0-7,k8-15),(n8-15,k0-7),(n8-15,k8-15)
    const uint32_t bAddr = sb + OFF_BH +
        (wn * 32 + ((lane >> 4) << 3) + (lane & 7)) * STRIDE + ((lane >> 3) & 1) * 16;

    for (int c = 0; c < 8; c++) {
        if (c < 7) { ISSUE(c + 1); CP_WAIT1(); } else { CP_WAIT0(); }
        __syncthreads();

        const uint32_t st = (uint32_t)((c & 1) * STAGE_B);
#pragma unroll
        for (int k16 = 0; k16 < 2; k16++) {
            const uint32_t kb = k16 * 32;

            // B fragments: 2 n-pairs x (hi, lo); regs {b0_nt, b1_nt, b0_nt+1, b1_nt+1}
            uint32_t bh[2][4], bl[2][4];
#pragma unroll
            for (int np = 0; np < 2; np++) {
                const uint32_t o = bAddr + st + np * (16 * STRIDE) + kb;
                ldsm4(bh[np], o);
                ldsm4(bl[np], o + TILE_B);
            }
#pragma unroll
            for (int mt = 0; mt < 4; mt++) {
                const uint32_t o = aAddr + st + mt * (16 * STRIDE) + kb;
                uint32_t ah[4], al[4];
                ldsm4(ah, o);
                ldsm4(al, o + OFF_AL);
#pragma unroll
                for (int np = 0; np < 2; np++) {
#pragma unroll
                    for (int half = 0; half < 2; half++) {
                        const int nt = np * 2 + half;
                        const uint32_t b0h = bh[np][half * 2], b1h = bh[np][half * 2 + 1];
                        const uint32_t b0l = bl[np][half * 2], b1l = bl[np][half * 2 + 1];
                        mma16816(acc[mt][nt], ah[0], ah[1], ah[2], ah[3], b0h, b1h);
                        mma16816(acc[mt][nt], ah[0], ah[1], ah[2], ah[3], b0l, b1l);
                        mma16816(acc[mt][nt], al[0], al[1], al[2], al[3], b0h, b1h);
                    }
                }
            }
        }
        __syncthreads();
    }

    // Epilogue: BN scale/offset + store
#pragma unroll
    for (int mt = 0; mt < 4; mt++) {
        const int row0 = bm + wm * 64 + mt * 16 + r;
#pragma unroll
        for (int nt = 0; nt < 4; nt++) {
            const int cl = wn * 32 + nt * 8 + tg * 2;   // local col
            const float i0 = sinv[cl], i1 = sinv[cl + 1];
            const float o0 = sbb[cl],  o1 = sbb[cl + 1];
            float2 v0, v1;
            v0.x = fmaf(acc[mt][nt][0], i0, o0);
            v0.y = fmaf(acc[mt][nt][1], i1, o1);
            v1.x = fmaf(acc[mt][nt][2], i0, o0);
            v1.y = fmaf(acc[mt][nt][3], i1, o1);
            *(float2*)(out + (size_t)row0 * CC + bn + cl)       = v0;
            *(float2*)(out + (size_t)(row0 + 8) * CC + bn + cl) = v1;
        }
    }
#undef ISSUE
}

// ---------------------------------------------------------------------------
// Launch
// ---------------------------------------------------------------------------
extern "C" void kernel_launch(void* const* d_in, const int* in_sizes, int n_in,
                              void* d_out, int out_size)
{
    const float* x     = (const float*)d_in[0];
    const float* dwk   = (const float*)d_in[1];
    const float* dwb   = (const float*)d_in[2];
    const float* pwk   = (const float*)d_in[3];
    const float* pwb   = (const float*)d_in[4];
    const float* gma   = (const float*)d_in[5];
    const float* bta   = (const float*)d_in[6];
    const float* mmean = (const float*)d_in[7];
    const float* mvar  = (const float*)d_in[8];
    float* out = (float*)d_out;

    static int smem_set = 0;
    if (!smem_set) {
        cudaFuncSetAttribute(gemm_mma_kernel,
                             cudaFuncAttributeMaxDynamicSharedMemorySize, SMEM_BYTES);
        smem_set = 1;
    }

    bprep_kernel<<<256, 256>>>(pwk);
    dw_relu_kernel<<<3136, 256>>>(x, dwk, dwb);
    gemm_mma_kernel<<<dim3(2, PP / 128), 256, SMEM_BYTES>>>(
        pwb, gma, bta, mmean, mvar, out);
}

// round 5
// speedup vs baseline: 2.5415x; 1.3838x over previous
#include <cuda_runtime.h>
#include <cuda_fp16.h>
#include <cstdint>

// Problem constants
#define NN 32
#define HH 56
#define WW 56
#define CC 256
#define PP (NN * HH * WW)   // 100352 pixels

// ---------------------------------------------------------------------------
// Scratch: depthwise output as plain fp16 (error 2^-11, absorbed by budget),
// pointwise weights transposed + fp16 hi/lo split: B[n][k] = bh + bl.
// ---------------------------------------------------------------------------
__device__ __align__(256) __half g_a[(size_t)PP * CC];
__device__ __align__(256) __half g_bh[CC * CC];
__device__ __align__(256) __half g_bl[CC * CC];

// ---------------------------------------------------------------------------
// PTX helpers
// ---------------------------------------------------------------------------
__device__ __forceinline__ uint32_t smem_u32(const void* p) {
    uint32_t a;
    asm("{ .reg .u64 t; cvta.to.shared.u64 t, %1; cvt.u32.u64 %0, t; }"
        : "=r"(a) : "l"(p));
    return a;
}
#define CP16(sa, gp) \
    asm volatile("cp.async.cg.shared.global [%0], [%1], 16;" \
                 :: "r"((uint32_t)(sa)), "l"(gp) : "memory")
#define CP_COMMIT() asm volatile("cp.async.commit_group;" ::: "memory")
#define CP_WAIT1()  asm volatile("cp.async.wait_group 1;" ::: "memory")

__device__ __forceinline__ void ldsm4(uint32_t r[4], uint32_t a) {
    asm volatile("ldmatrix.sync.aligned.m8n8.x4.shared.b16 {%0,%1,%2,%3}, [%4];"
                 : "=r"(r[0]), "=r"(r[1]), "=r"(r[2]), "=r"(r[3]) : "r"(a));
}
__device__ __forceinline__ void mma16816(float c[4],
                                         uint32_t a0, uint32_t a1, uint32_t a2, uint32_t a3,
                                         uint32_t b0, uint32_t b1) {
    asm volatile(
        "mma.sync.aligned.m16n8k16.row.col.f32.f16.f16.f32 "
        "{%0,%1,%2,%3}, {%4,%5,%6,%7}, {%8,%9}, {%0,%1,%2,%3};"
        : "+f"(c[0]), "+f"(c[1]), "+f"(c[2]), "+f"(c[3])
        : "r"(a0), "r"(a1), "r"(a2), "r"(a3), "r"(b0), "r"(b1));
}

__device__ __forceinline__ void store_h4(__half* p, float4 v) {
    __half2 a = __floats2half2_rn(v.x, v.y);
    __half2 b = __floats2half2_rn(v.z, v.w);
    uint2 u;
    u.x = *(uint32_t*)&a;
    u.y = *(uint32_t*)&b;
    *(uint2*)p = u;
}

// ---------------------------------------------------------------------------
// Kernel 0: transpose + fp16-split pw_kernel -> g_bh/g_bl [n][k]
// ---------------------------------------------------------------------------
__global__ void __launch_bounds__(256) bprep_kernel(const float* __restrict__ pwk) {
    const int idx = blockIdx.x * 256 + threadIdx.x;  // 65536 total
    const int k = idx >> 8, n = idx & 255;
    const float v = pwk[(size_t)k * CC + n];
    const __half h = __float2half_rn(v);
    const __half l = __float2half_rn(v - __half2float(h));
    g_bh[(size_t)n * CC + k] = h;
    g_bl[(size_t)n * CC + k] = l;
}

// ---------------------------------------------------------------------------
// Kernel 1: ReLU + dilated 3x3 depthwise (rate 2) + dw_bias -> fp16.
// 8 consecutive w pixels per thread share input columns (12 loads / 24 taps).
// ---------------------------------------------------------------------------
__global__ void __launch_bounds__(256) dw_relu_kernel(
    const float* __restrict__ x,
    const float* __restrict__ dwk,
    const float* __restrict__ dwb)
{
    const int t = threadIdx.x;
    const int c = (t & 63) * 4;                    // channel group
    const int oct = blockIdx.x * 4 + (t >> 6);     // 0..12543
    const int w0 = (oct % 7) * 8;
    const int nh = oct / 7;
    const int h = nh % HH;
    const int n = nh / HH;

    float4 k[9];
#pragma unroll
    for (int tap = 0; tap < 9; tap++)
        k[tap] = *(const float4*)(dwk + tap * CC + c);
    const float4 bias = *(const float4*)(dwb + c);

    float4 acc[8];
#pragma unroll
    for (int px = 0; px < 8; px++) acc[px] = bias;

#pragma unroll
    for (int kh = 0; kh < 3; kh++) {
        const int hh = h + 2 * kh - 2;
        if ((unsigned)hh >= (unsigned)HH) continue;
        const float* xrow = x + ((size_t)(n * HH + hh) * WW) * CC + c;

        float4 col[12];
#pragma unroll
        for (int j = 0; j < 12; j++) {
            const int ww = w0 - 2 + j;
            if ((unsigned)ww < (unsigned)WW) {
                float4 v = *(const float4*)(xrow + (size_t)ww * CC);
                v.x = fmaxf(v.x, 0.0f); v.y = fmaxf(v.y, 0.0f);
                v.z = fmaxf(v.z, 0.0f); v.w = fmaxf(v.w, 0.0f);
                col[j] = v;
            } else {
                col[j] = make_float4(0.f, 0.f, 0.f, 0.f);
            }
        }
        const float4 k0 = k[kh * 3 + 0], k1 = k[kh * 3 + 1], k2 = k[kh * 3 + 2];
#pragma unroll
        for (int px = 0; px < 8; px++) {
            acc[px].x = fmaf(col[px].x, k0.x, fmaf(col[px + 2].x, k1.x, fmaf(col[px + 4].x, k2.x, acc[px].x)));
            acc[px].y = fmaf(col[px].y, k0.y, fmaf(col[px + 2].y, k1.y, fmaf(col[px + 4].y, k2.y, acc[px].y)));
            acc[px].z = fmaf(col[px].z, k0.z, fmaf(col[px + 2].z, k1.z, fmaf(col[px + 4].z, k2.z, acc[px].z)));
            acc[px].w = fmaf(col[px].w, k0.w, fmaf(col[px + 2].w, k1.w, fmaf(col[px + 4].w, k2.w, acc[px].w)));
        }
    }

    const size_t base = ((size_t)(n * HH + h) * WW + w0) * CC + c;
#pragma unroll
    for (int px = 0; px < 8; px++)
        store_h4(g_a + base + (size_t)px * CC, acc[px]);
}

// ---------------------------------------------------------------------------
// Kernel 2: HMMA fp16 split-GEMM [P,256]x[256,256] + bias + BN.
// CTA 128x128, 8 warps (2m x 4n), warp tile 64x32, K chunks of 32.
// D = A*Bh + A*Bl  (2 MMAs per fragment pair; A plain fp16, B fp16 hi/lo).
// 3-stage cp.async pipeline, ONE barrier per chunk.
// Smem rows padded to 80B (conflict-free for ldmatrix 8-row phases).
// Grid (bn=2, bm=784): CTAs sharing an A tile run adjacently -> L2 reuse.
// ---------------------------------------------------------------------------
#define STRIDE 80
#define TILE_B (128 * STRIDE)          // 10240 bytes per [128][32] fp16 tile
#define OFF_BH TILE_B
#define OFF_BL (2 * TILE_B)
#define STAGE_B (3 * TILE_B)           // A, Bh, Bl = 30720
#define OFF_INV (3 * STAGE_B)          // 92160
#define OFF_B2  (OFF_INV + 512)
#define SMEM_BYTES (OFF_B2 + 512)      // 93184

__global__ void __launch_bounds__(256, 2) gemm_mma_kernel(
    const float* __restrict__ pwb,
    const float* __restrict__ gma,
    const float* __restrict__ bta,
    const float* __restrict__ mmean,
    const float* __restrict__ mvar,
    float* __restrict__ out)
{
    extern __shared__ __align__(128) char smem[];
    const uint32_t sb = smem_u32(smem);
    const int t = threadIdx.x;
    const int lane = t & 31, wid = t >> 5;
    const int wm = wid & 1, wn = wid >> 1;
    const int r = lane >> 2, tg = lane & 3;
    const int bn = blockIdx.x * 128;
    const int bm = blockIdx.y * 128;

    // BN constants
    float* sinv = (float*)(smem + OFF_INV);
    float* sbb  = (float*)(smem + OFF_B2);
    if (t < 128) {
        const int nn = bn + t;
        const float iv = gma[nn] * rsqrtf(mvar[nn] + 1e-3f);
        sinv[t] = iv;
        sbb[t]  = fmaf(pwb[nn], iv, bta[nn] - mmean[nn] * iv);
    }

    // loader addressing: thread t -> row t>>1, 32B half (t&1)
    const int lrow = t >> 1, lhalf = t & 1;
    const __half* gA  = g_a  + (size_t)(bm + lrow) * CC + lhalf * 16;
    const __half* gBh = g_bh + (size_t)(bn + lrow) * CC + lhalf * 16;
    const __half* gBl = g_bl + (size_t)(bn + lrow) * CC + lhalf * 16;
    const uint32_t sdst = sb + lrow * STRIDE + lhalf * 32;

#define ISSUE(k0, stoff) do {                                               \
    CP16(sdst + (stoff) + 0,            gA  + (k0));                        \
    CP16(sdst + (stoff) + 16,           gA  + (k0) + 8);                    \
    CP16(sdst + (stoff) + OFF_BH,       gBh + (k0));                        \
    CP16(sdst + (stoff) + OFF_BH + 16,  gBh + (k0) + 8);                    \
    CP16(sdst + (stoff) + OFF_BL,       gBl + (k0));                        \
    CP16(sdst + (stoff) + OFF_BL + 16,  gBl + (k0) + 8);                    \
    CP_COMMIT();                                                            \
} while (0)

    // prologue: stages 0 and 1
    ISSUE(0, 0);
    ISSUE(32, STAGE_B);

    float acc[4][4][4];
#pragma unroll
    for (int mt = 0; mt < 4; mt++)
#pragma unroll
        for (int nt = 0; nt < 4; nt++)
#pragma unroll
            for (int i = 0; i < 4; i++) acc[mt][nt][i] = 0.0f;

    // ldmatrix lane addresses (offsets within a stage)
    const uint32_t aAddr = sb + (wm * 64 + (lane & 15)) * STRIDE + (lane >> 4) * 16;
    const uint32_t bAddr = sb + OFF_BH +
        (wn * 32 + ((lane >> 4) << 3) + (lane & 7)) * STRIDE + ((lane >> 3) & 1) * 16;

    uint32_t st = 0;                 // compute-stage byte offset
    uint32_t ist = 2 * STAGE_B;      // issue-stage byte offset

    for (int c = 0; c < 8; c++) {
        CP_WAIT1();                  // stage c complete
        __syncthreads();             // visibility + protects buffer reuse
        if (c < 6) {
            ISSUE((c + 2) * 32, ist);
            ist = (ist == 2 * STAGE_B) ? 0u : ist + STAGE_B;
        } else {
            CP_COMMIT();             // keep group counting aligned
        }

#pragma unroll
        for (int k16 = 0; k16 < 2; k16++) {
            const uint32_t kb = k16 * 32;

            uint32_t bh[2][4], bl[2][4];
#pragma unroll
            for (int np = 0; np < 2; np++) {
                const uint32_t o = bAddr + st + np * (16 * STRIDE) + kb;
                ldsm4(bh[np], o);
                ldsm4(bl[np], o + TILE_B);   // Bl sits one tile above Bh
            }
#pragma unroll
            for (int mt = 0; mt < 4; mt++) {
                uint32_t a[4];
                ldsm4(a, aAddr + st + mt * (16 * STRIDE) + kb);
#pragma unroll
                for (int np = 0; np < 2; np++) {
#pragma unroll
                    for (int half = 0; half < 2; half++) {
                        const int nt = np * 2 + half;
                        mma16816(acc[mt][nt], a[0], a[1], a[2], a[3],
                                 bh[np][half * 2], bh[np][half * 2 + 1]);
                        mma16816(acc[mt][nt], a[0], a[1], a[2], a[3],
                                 bl[np][half * 2], bl[np][half * 2 + 1]);
                    }
                }
            }
        }
        st = (st == 2 * STAGE_B) ? 0u : st + STAGE_B;
    }

    // Epilogue: BN scale/offset + store
#pragma unroll
    for (int mt = 0; mt < 4; mt++) {
        const int row0 = bm + wm * 64 + mt * 16 + r;
#pragma unroll
        for (int nt = 0; nt < 4; nt++) {
            const int cl = wn * 32 + nt * 8 + tg * 2;   // local col
            const float i0 = sinv[cl], i1 = sinv[cl + 1];
            const float o0 = sbb[cl],  o1 = sbb[cl + 1];
            float2 v0, v1;
            v0.x = fmaf(acc[mt][nt][0], i0, o0);
            v0.y = fmaf(acc[mt][nt][1], i1, o1);
            v1.x = fmaf(acc[mt][nt][2], i0, o0);
            v1.y = fmaf(acc[mt][nt][3], i1, o1);
            *(float2*)(out + (size_t)row0 * CC + bn + cl)       = v0;
            *(float2*)(out + (size_t)(row0 + 8) * CC + bn + cl) = v1;
        }
    }
#undef ISSUE
}

// ---------------------------------------------------------------------------
// Launch
// ---------------------------------------------------------------------------
extern "C" void kernel_launch(void* const* d_in, const int* in_sizes, int n_in,
                              void* d_out, int out_size)
{
    const float* x     = (const float*)d_in[0];
    const float* dwk   = (const float*)d_in[1];
    const float* dwb   = (const float*)d_in[2];
    const float* pwk   = (const float*)d_in[3];
    const float* pwb   = (const float*)d_in[4];
    const float* gma   = (const float*)d_in[5];
    const float* bta   = (const float*)d_in[6];
    const float* mmean = (const float*)d_in[7];
    const float* mvar  = (const float*)d_in[8];
    float* out = (float*)d_out;

    static int smem_set = 0;
    if (!smem_set) {
        cudaFuncSetAttribute(gemm_mma_kernel,
                             cudaFuncAttributeMaxDynamicSharedMemorySize, SMEM_BYTES);
        smem_set = 1;
    }

    bprep_kernel<<<256, 256>>>(pwk);
    dw_relu_kernel<<<3136, 256>>>(x, dwk, dwb);
    gemm_mma_kernel<<<dim3(2, PP / 128), 256, SMEM_BYTES>>>(
        pwb, gma, bta, mmean, mvar, out);
}

// round 6
// speedup vs baseline: 3.0723x; 1.2089x over previous
#include <cuda_runtime.h>
#include <cuda_fp16.h>
#include <cstdint>

// Problem constants
#define NN 32
#define HH 56
#define WW 56
#define CC 256
#define PP (NN * HH * WW)   // 100352 pixels

// ---------------------------------------------------------------------------
// Scratch: depthwise output as fp16, pointwise weights transposed fp16 B[n][k].
// Error budget (calibrated R4/R5): A-round 1.8e-4 + B-round 1.8e-4 -> ~2.6e-4.
// ---------------------------------------------------------------------------
__device__ __align__(256) __half g_a[(size_t)PP * CC];
__device__ __align__(256) __half g_b[CC * CC];

// ---------------------------------------------------------------------------
// PTX helpers
// ---------------------------------------------------------------------------
__device__ __forceinline__ uint32_t smem_u32(const void* p) {
    uint32_t a;
    asm("{ .reg .u64 t; cvta.to.shared.u64 t, %1; cvt.u32.u64 %0, t; }"
        : "=r"(a) : "l"(p));
    return a;
}
#define CP16(sa, gp) \
    asm volatile("cp.async.cg.shared.global [%0], [%1], 16;" \
                 :: "r"((uint32_t)(sa)), "l"(gp) : "memory")
#define CP_COMMIT() asm volatile("cp.async.commit_group;" ::: "memory")
#define CP_WAIT2()  asm volatile("cp.async.wait_group 2;" ::: "memory")

__device__ __forceinline__ void ldsm4(uint32_t r[4], uint32_t a) {
    asm volatile("ldmatrix.sync.aligned.m8n8.x4.shared.b16 {%0,%1,%2,%3}, [%4];"
                 : "=r"(r[0]), "=r"(r[1]), "=r"(r[2]), "=r"(r[3]) : "r"(a));
}
__device__ __forceinline__ void mma16816(float c[4],
                                         uint32_t a0, uint32_t a1, uint32_t a2, uint32_t a3,
                                         uint32_t b0, uint32_t b1) {
    asm volatile(
        "mma.sync.aligned.m16n8k16.row.col.f32.f16.f16.f32 "
        "{%0,%1,%2,%3}, {%4,%5,%6,%7}, {%8,%9}, {%0,%1,%2,%3};"
        : "+f"(c[0]), "+f"(c[1]), "+f"(c[2]), "+f"(c[3])
        : "r"(a0), "r"(a1), "r"(a2), "r"(a3), "r"(b0), "r"(b1));
}

__device__ __forceinline__ void store_h4(__half* p, float4 v) {
    __half2 a = __floats2half2_rn(v.x, v.y);
    __half2 b = __floats2half2_rn(v.z, v.w);
    uint2 u;
    u.x = *(uint32_t*)&a;
    u.y = *(uint32_t*)&b;
    *(uint2*)p = u;
}

// ---------------------------------------------------------------------------
// Kernel 0: transpose pw_kernel -> g_b [n][k] fp16
// ---------------------------------------------------------------------------
__global__ void __launch_bounds__(256) bprep_kernel(const float* __restrict__ pwk) {
    const int idx = blockIdx.x * 256 + threadIdx.x;  // 65536 total
    const int k = idx >> 8, n = idx & 255;
    g_b[(size_t)n * CC + k] = __float2half_rn(pwk[(size_t)k * CC + n]);
}

// ---------------------------------------------------------------------------
// Kernel 1: ReLU + dilated 3x3 depthwise (rate 2) + dw_bias -> fp16.
// 8 consecutive w pixels per thread share input columns (12 loads / 24 taps).
// ---------------------------------------------------------------------------
__global__ void __launch_bounds__(256) dw_relu_kernel(
    const float* __restrict__ x,
    const float* __restrict__ dwk,
    const float* __restrict__ dwb)
{
    const int t = threadIdx.x;
    const int c = (t & 63) * 4;                    // channel group
    const int oct = blockIdx.x * 4 + (t >> 6);     // 0..12543
    const int w0 = (oct % 7) * 8;
    const int nh = oct / 7;
    const int h = nh % HH;
    const int n = nh / HH;

    float4 k[9];
#pragma unroll
    for (int tap = 0; tap < 9; tap++)
        k[tap] = *(const float4*)(dwk + tap * CC + c);
    const float4 bias = *(const float4*)(dwb + c);

    float4 acc[8];
#pragma unroll
    for (int px = 0; px < 8; px++) acc[px] = bias;

#pragma unroll
    for (int kh = 0; kh < 3; kh++) {
        const int hh = h + 2 * kh - 2;
        if ((unsigned)hh >= (unsigned)HH) continue;
        const float* xrow = x + ((size_t)(n * HH + hh) * WW) * CC + c;

        float4 col[12];
#pragma unroll
        for (int j = 0; j < 12; j++) {
            const int ww = w0 - 2 + j;
            if ((unsigned)ww < (unsigned)WW) {
                float4 v = *(const float4*)(xrow + (size_t)ww * CC);
                v.x = fmaxf(v.x, 0.0f); v.y = fmaxf(v.y, 0.0f);
                v.z = fmaxf(v.z, 0.0f); v.w = fmaxf(v.w, 0.0f);
                col[j] = v;
            } else {
                col[j] = make_float4(0.f, 0.f, 0.f, 0.f);
            }
        }
        const float4 k0 = k[kh * 3 + 0], k1 = k[kh * 3 + 1], k2 = k[kh * 3 + 2];
#pragma unroll
        for (int px = 0; px < 8; px++) {
            acc[px].x = fmaf(col[px].x, k0.x, fmaf(col[px + 2].x, k1.x, fmaf(col[px + 4].x, k2.x, acc[px].x)));
            acc[px].y = fmaf(col[px].y, k0.y, fmaf(col[px + 2].y, k1.y, fmaf(col[px + 4].y, k2.y, acc[px].y)));
            acc[px].z = fmaf(col[px].z, k0.z, fmaf(col[px + 2].z, k1.z, fmaf(col[px + 4].z, k2.z, acc[px].z)));
            acc[px].w = fmaf(col[px].w, k0.w, fmaf(col[px + 2].w, k1.w, fmaf(col[px + 4].w, k2.w, acc[px].w)));
        }
    }

    const size_t base = ((size_t)(n * HH + h) * WW + w0) * CC + c;
#pragma unroll
    for (int px = 0; px < 8; px++)
        store_h4(g_a + base + (size_t)px * CC, acc[px]);
}

// ---------------------------------------------------------------------------
// Kernel 2: HMMA fp16 GEMM [P,256]x[256,256] + bias + BN.
// CTA 128x128, 8 warps (2m x 4n), warp tile 64x32, K chunks of 32.
// 4-stage cp.async pipeline (wait_group 2), one barrier per chunk.
// Smem rows padded to 80B (conflict-free for ldmatrix 8-row phases).
// Grid (bn=2, bm=784): CTAs sharing an A tile run adjacently -> L2 reuse.
// ---------------------------------------------------------------------------
#define STRIDE 80
#define TILE_B (128 * STRIDE)          // 10240 bytes per [128][32] fp16 tile
#define OFF_B TILE_B
#define STAGE_B (2 * TILE_B)           // A, B = 20480
#define OFF_INV (4 * STAGE_B)          // 81920
#define OFF_B2  (OFF_INV + 512)
#define SMEM_BYTES (OFF_B2 + 512)      // 82944

__global__ void __launch_bounds__(256, 2) gemm_mma_kernel(
    const float* __restrict__ pwb,
    const float* __restrict__ gma,
    const float* __restrict__ bta,
    const float* __restrict__ mmean,
    const float* __restrict__ mvar,
    float* __restrict__ out)
{
    extern __shared__ __align__(128) char smem[];
    const uint32_t sb = smem_u32(smem);
    const int t = threadIdx.x;
    const int lane = t & 31, wid = t >> 5;
    const int wm = wid & 1, wn = wid >> 1;
    const int r = lane >> 2, tg = lane & 3;
    const int bn = blockIdx.x * 128;
    const int bm = blockIdx.y * 128;

    // BN constants
    float* sinv = (float*)(smem + OFF_INV);
    float* sbb  = (float*)(smem + OFF_B2);
    if (t < 128) {
        const int nn = bn + t;
        const float iv = gma[nn] * rsqrtf(mvar[nn] + 1e-3f);
        sinv[t] = iv;
        sbb[t]  = fmaf(pwb[nn], iv, bta[nn] - mmean[nn] * iv);
    }

    // loader addressing: thread t -> row t>>1, 32B half (t&1)
    const int lrow = t >> 1, lhalf = t & 1;
    const __half* gA = g_a + (size_t)(bm + lrow) * CC + lhalf * 16;
    const __half* gB = g_b + (size_t)(bn + lrow) * CC + lhalf * 16;
    const uint32_t sdst = sb + lrow * STRIDE + lhalf * 32;

#define ISSUE(k0, stoff) do {                                               \
    CP16(sdst + (stoff) + 0,           gA + (k0));                          \
    CP16(sdst + (stoff) + 16,          gA + (k0) + 8);                      \
    CP16(sdst + (stoff) + OFF_B,       gB + (k0));                          \
    CP16(sdst + (stoff) + OFF_B + 16,  gB + (k0) + 8);                      \
    CP_COMMIT();                                                            \
} while (0)

    // prologue: stages 0..2
    ISSUE(0, 0);
    ISSUE(32, STAGE_B);
    ISSUE(64, 2 * STAGE_B);

    float acc[4][4][4];
#pragma unroll
    for (int mt = 0; mt < 4; mt++)
#pragma unroll
        for (int nt = 0; nt < 4; nt++)
#pragma unroll
            for (int i = 0; i < 4; i++) acc[mt][nt][i] = 0.0f;

    // ldmatrix lane addresses (offsets within a stage)
    const uint32_t aAddr = sb + (wm * 64 + (lane & 15)) * STRIDE + (lane >> 4) * 16;
    const uint32_t bAddr = sb + OFF_B +
        (wn * 32 + ((lane >> 4) << 3) + (lane & 7)) * STRIDE + ((lane >> 3) & 1) * 16;

    uint32_t st = 0;                 // compute-stage byte offset
    uint32_t ist = 3 * STAGE_B;      // issue-stage byte offset

    for (int c = 0; c < 8; c++) {
        CP_WAIT2();                  // stage c complete (<=2 groups pending)
        __syncthreads();             // visibility + protects buffer (c-1)%4 reuse
        if (c < 5) {
            ISSUE((c + 3) * 32, ist);
            ist = (ist == 3 * STAGE_B) ? 0u : ist + STAGE_B;
        } else {
            CP_COMMIT();             // keep group counting aligned
        }

#pragma unroll
        for (int k16 = 0; k16 < 2; k16++) {
            const uint32_t kb = k16 * 32;

            uint32_t bf[2][4];
#pragma unroll
            for (int np = 0; np < 2; np++)
                ldsm4(bf[np], bAddr + st + np * (16 * STRIDE) + kb);
#pragma unroll
            for (int mt = 0; mt < 4; mt++) {
                uint32_t a[4];
                ldsm4(a, aAddr + st + mt * (16 * STRIDE) + kb);
#pragma unroll
                for (int np = 0; np < 2; np++) {
#pragma unroll
                    for (int half = 0; half < 2; half++) {
                        const int nt = np * 2 + half;
                        mma16816(acc[mt][nt], a[0], a[1], a[2], a[3],
                                 bf[np][half * 2], bf[np][half * 2 + 1]);
                    }
                }
            }
        }
        st = (st == 3 * STAGE_B) ? 0u : st + STAGE_B;
    }

    // Epilogue: BN scale/offset + store
#pragma unroll
    for (int mt = 0; mt < 4; mt++) {
        const int row0 = bm + wm * 64 + mt * 16 + r;
#pragma unroll
        for (int nt = 0; nt < 4; nt++) {
            const int cl = wn * 32 + nt * 8 + tg * 2;   // local col
            const float i0 = sinv[cl], i1 = sinv[cl + 1];
            const float o0 = sbb[cl],  o1 = sbb[cl + 1];
            float2 v0, v1;
            v0.x = fmaf(acc[mt][nt][0], i0, o0);
            v0.y = fmaf(acc[mt][nt][1], i1, o1);
            v1.x = fmaf(acc[mt][nt][2], i0, o0);
            v1.y = fmaf(acc[mt][nt][3], i1, o1);
            *(float2*)(out + (size_t)row0 * CC + bn + cl)       = v0;
            *(float2*)(out + (size_t)(row0 + 8) * CC + bn + cl) = v1;
        }
    }
#undef ISSUE
}

// ---------------------------------------------------------------------------
// Launch
// ---------------------------------------------------------------------------
extern "C" void kernel_launch(void* const* d_in, const int* in_sizes, int n_in,
                              void* d_out, int out_size)
{
    const float* x     = (const float*)d_in[0];
    const float* dwk   = (const float*)d_in[1];
    const float* dwb   = (const float*)d_in[2];
    const float* pwk   = (const float*)d_in[3];
    const float* pwb   = (const float*)d_in[4];
    const float* gma   = (const float*)d_in[5];
    const float* bta   = (const float*)d_in[6];
    const float* mmean = (const float*)d_in[7];
    const float* mvar  = (const float*)d_in[8];
    float* out = (float*)d_out;

    static int smem_set = 0;
    if (!smem_set) {
        cudaFuncSetAttribute(gemm_mma_kernel,
                             cudaFuncAttributeMaxDynamicSharedMemorySize, SMEM_BYTES);
        smem_set = 1;
    }

    bprep_kernel<<<256, 256>>>(pwk);
    dw_relu_kernel<<<3136, 256>>>(x, dwk, dwb);
    gemm_mma_kernel<<<dim3(2, PP / 128), 256, SMEM_BYTES>>>(
        pwb, gma, bta, mmean, mvar, out);
}